// round 15
// baseline (speedup 1.0000x reference)
#include <cuda_runtime.h>
#include <math.h>

// ---------------- problem constants ----------------
#define NMAX   50000
#define EMAX   800000
#define FD     128
#define BGRAPH 100

typedef unsigned long long u64;

// ---------------- scratch (device globals; no allocation) ----------------
__device__ float g_xcur[NMAX * FD];            // current node features
__device__ float g_nds [(size_t)NMAX * 384];   // [xd | xs | -]
__device__ float g_xP0 [NMAX * FD];            // x@P0 for selected rows
__device__ float g_Y   [(size_t)NMAX * 384];   // [Y1 | Y2 | Y3] (selected rows)
__device__ float g_Amat[(size_t)NMAX * 640];   // [mean|mn|mx|std|sum]
__device__ float g_sa[NMAX];
__device__ float g_sb[NMAX];
__device__ int   g_src[EMAX];
__device__ int   g_dst[EMAX];
__device__ unsigned char g_emask[EMAX];
__device__ int   g_deg[NMAX + 1];
__device__ int   g_rowptr[NMAX + 1];
__device__ int   g_cursor[NMAX];
__device__ int   g_elist[EMAX];
__device__ int   g_newidx[NMAX];
__device__ int   g_selidx[NMAX];               // new index -> original node
__device__ float g_vals[NMAX];                 // new index -> topk score value
__device__ float g_score[NMAX];
__device__ float g_Wc[8 * FD];                 // edge_w @ We  (8x128)
__device__ float g_cvec[FD];                   // edge_b@We + pre_b
__device__ float g_PW[2048 * FD];              // post_w @ lin_w
__device__ float g_B1[128 * 384];              // [Wd | Ws | P0]
__device__ float g_B2[640 * 384];              // [P1 | P2 | P3]
__device__ float g_u[2048];                    // PW @ pool_w
__device__ float g_pb[FD];                     // post_b@lin_w + lin_b
__device__ float g_winv;                       // 1/||pool_w||
__device__ float g_pbw;                        // pb . pool_w
__device__ float g_bnsum[FD];
__device__ float g_bnsq [FD];

// ---------------- packed f32x2 helpers ----------------
__device__ __forceinline__ u64 dup2(float v) {
    u64 r; unsigned u = __float_as_uint(v);
    asm("mov.b64 %0, {%1, %1};" : "=l"(r) : "r"(u));
    return r;
}
__device__ __forceinline__ void fma2(u64& d, u64 a, u64 b) {
    asm("fma.rn.f32x2 %0, %1, %2, %0;" : "+l"(d) : "l"(a), "l"(b));
}
__device__ __forceinline__ float lo2(u64 v) { return __uint_as_float((unsigned)v); }
__device__ __forceinline__ float hi2(u64 v) { return __uint_as_float((unsigned)(v >> 32)); }

// ---------------- small init / utility kernels ----------------
__global__ void k_init_edges(const int* __restrict__ ei) {
    int i = blockIdx.x * blockDim.x + threadIdx.x;
    if (i >= EMAX) return;
    g_src[i] = ei[i];
    g_dst[i] = ei[EMAX + i];
    g_emask[i] = 1;
}

// deg zero + newidx fill + bn zero, one kernel
__global__ void k_reset(int N) {
    int i = blockIdx.x * blockDim.x + threadIdx.x;
    if (i <= N) g_deg[i] = 0;
    if (i < N) g_newidx[i] = -1;
    if (i < FD) { g_bnsum[i] = 0.f; g_bnsq[i] = 0.f; }
}

// ---------------- per-layer weight prep ----------------
__global__ void k_prep(const float* __restrict__ ew, const float* __restrict__ eb,
                       const float* __restrict__ We, const float* __restrict__ preb,
                       const float* __restrict__ postb, const float* __restrict__ linw,
                       const float* __restrict__ linb, const float* __restrict__ poolw) {
    int f = threadIdx.x;  // 0..127
    for (int jr = 0; jr < 8; jr++) {
        float acc = 0.f;
        for (int t = 0; t < FD; t++) acc += ew[jr * FD + t] * We[t * FD + f];
        g_Wc[jr * FD + f] = acc;
    }
    float c = preb[f];
    for (int t = 0; t < FD; t++) c += eb[t] * We[t * FD + f];
    g_cvec[f] = c;
    float p = linb[f];
    for (int t = 0; t < FD; t++) p += postb[t] * linw[t * FD + f];
    g_pb[f] = p;

    __shared__ float red[FD];
    red[f] = poolw[f] * poolw[f];
    __syncthreads();
    for (int off = 64; off > 0; off >>= 1) {
        if (f < off) red[f] += red[f + off];
        __syncthreads();
    }
    if (f == 0) g_winv = 1.f / sqrtf(red[0]);
    __syncthreads();
    red[f] = p * poolw[f];
    __syncthreads();
    for (int off = 64; off > 0; off >>= 1) {
        if (f < off) red[f] += red[f + off];
        __syncthreads();
    }
    if (f == 0) g_pbw = red[0];
}

// u = PW @ pool_w  (2048-vector), warp per row
__global__ void k_prepU(const float* __restrict__ poolw) {
    int warp = (blockIdx.x * blockDim.x + threadIdx.x) >> 5;
    int lane = threadIdx.x & 31;
    if (warp >= 2048) return;
    const float4* row = (const float4*)(g_PW + (size_t)warp * FD);
    float4 r = row[lane];
    float4 w = *(const float4*)&poolw[lane * 4];
    float acc = r.x * w.x + r.y * w.y + r.z * w.z + r.w * w.w;
    for (int off = 16; off > 0; off >>= 1) acc += __shfl_down_sync(0xffffffffu, acc, off);
    if (lane == 0) g_u[warp] = acc;
}

// pack B1 = [Wd | Ws | P0]  (128 x 384)  (P0 block kept for layout; unused by y=2 launch)
__global__ void k_packB1(const float* __restrict__ pw_l) {
    int i = blockIdx.x * blockDim.x + threadIdx.x;
    if (i >= 128 * 384) return;
    int k = i / 384, c = i % 384;
    float v;
    if (c < 128)      v = pw_l[k * 128 + c];
    else if (c < 256) v = pw_l[(128 + k) * 128 + (c - 128)];
    else              v = g_PW[k * 128 + (c - 256)];
    g_B1[i] = v;
}

// pack B2 = [P1 | P2 | P3] (640 x 384)
__global__ void k_packB2() {
    int i = blockIdx.x * blockDim.x + threadIdx.x;
    if (i >= 640 * 384) return;
    int k = i / 384, c = i % 384;
    g_B2[i] = g_PW[(size_t)(128 + (c >> 7) * 640 + k) * 128 + (c & 127)];
}

// ---------------- fp32 GEMM, double-buffered, packed FFMA2, row-gather -----
#define TK 16
__global__ __launch_bounds__(256, 2) void k_gemm3(
    const float* __restrict__ A, const float* __restrict__ B,
    float* __restrict__ C, int M, int K, int ldb, const int* __restrict__ rmap)
{
    __shared__ float As[2][TK][132];
    __shared__ float Bs[2][TK][128];
    int t  = threadIdx.x;
    int tx = t & 15;
    int ty = t >> 4;
    int rowBase = blockIdx.x * 128;
    int colBase = blockIdx.y * 128;

    int ar  = t >> 2;
    int akc = (t & 3) * 4;
    int brow = t >> 5;
    int bcol = (t & 31) * 4;

    int row0 = rowBase + ar;
    int row1 = rowBase + ar + 64;
    bool v0 = row0 < M, v1 = row1 < M;
    int gr0 = v0 ? (rmap ? rmap[row0] : row0) : 0;
    int gr1 = v1 ? (rmap ? rmap[row1] : row1) : 0;
    const float* a0p = A + (size_t)gr0 * K + akc;
    const float* a1p = A + (size_t)gr1 * K + akc;
    const float* b0p = B + (size_t)brow * ldb + colBase + bcol;
    const float* b1p = B + (size_t)(brow + 8) * ldb + colBase + bcol;

    float4 ra0, ra1, rb0, rb1;
    const float4 z4 = make_float4(0.f, 0.f, 0.f, 0.f);

    ra0 = v0 ? *(const float4*)a0p : z4;
    ra1 = v1 ? *(const float4*)a1p : z4;
    rb0 = *(const float4*)b0p;
    rb1 = *(const float4*)b1p;

    As[0][akc + 0][ar] = ra0.x; As[0][akc + 1][ar] = ra0.y;
    As[0][akc + 2][ar] = ra0.z; As[0][akc + 3][ar] = ra0.w;
    As[0][akc + 0][ar + 64] = ra1.x; As[0][akc + 1][ar + 64] = ra1.y;
    As[0][akc + 2][ar + 64] = ra1.z; As[0][akc + 3][ar + 64] = ra1.w;
    *(float4*)&Bs[0][brow][bcol]     = rb0;
    *(float4*)&Bs[0][brow + 8][bcol] = rb1;
    __syncthreads();

    u64 acc2[8][4];
#pragma unroll
    for (int i = 0; i < 8; i++)
#pragma unroll
        for (int j = 0; j < 4; j++) acc2[i][j] = 0ull;

    union F4U2 { float4 f; u64 u[2]; };

    int nT = K / TK;
    int buf = 0;
    for (int tile = 0; tile < nT; tile++) {
        if (tile + 1 < nT) {
            int kb = (tile + 1) * TK;
            ra0 = v0 ? *(const float4*)(a0p + kb) : z4;
            ra1 = v1 ? *(const float4*)(a1p + kb) : z4;
            rb0 = *(const float4*)(b0p + (size_t)kb * ldb);
            rb1 = *(const float4*)(b1p + (size_t)kb * ldb);
        }
#pragma unroll
        for (int kk = 0; kk < TK; kk++) {
            float a[8];
            *(float4*)&a[0] = *(float4*)&As[buf][kk][ty * 8];
            *(float4*)&a[4] = *(float4*)&As[buf][kk][ty * 8 + 4];
            F4U2 bA, bB;
            bA.f = *(float4*)&Bs[buf][kk][tx * 8];
            bB.f = *(float4*)&Bs[buf][kk][tx * 8 + 4];
            u64 bp0 = bA.u[0], bp1 = bA.u[1], bp2 = bB.u[0], bp3 = bB.u[1];
#pragma unroll
            for (int i = 0; i < 8; i++) {
                u64 a2 = dup2(a[i]);
                fma2(acc2[i][0], a2, bp0);
                fma2(acc2[i][1], a2, bp1);
                fma2(acc2[i][2], a2, bp2);
                fma2(acc2[i][3], a2, bp3);
            }
        }
        if (tile + 1 < nT) {
            int nb = buf ^ 1;
            As[nb][akc + 0][ar] = ra0.x; As[nb][akc + 1][ar] = ra0.y;
            As[nb][akc + 2][ar] = ra0.z; As[nb][akc + 3][ar] = ra0.w;
            As[nb][akc + 0][ar + 64] = ra1.x; As[nb][akc + 1][ar + 64] = ra1.y;
            As[nb][akc + 2][ar + 64] = ra1.z; As[nb][akc + 3][ar + 64] = ra1.w;
            *(float4*)&Bs[nb][brow][bcol]     = rb0;
            *(float4*)&Bs[nb][brow + 8][bcol] = rb1;
            __syncthreads();
            buf = nb;
        }
    }
#pragma unroll
    for (int i = 0; i < 8; i++) {
        int row = rowBase + ty * 8 + i;
        if (row < M) {
            float* crow = C + (size_t)row * ldb + colBase + tx * 8;
            *(float4*)&crow[0] = make_float4(lo2(acc2[i][0]), hi2(acc2[i][0]),
                                             lo2(acc2[i][1]), hi2(acc2[i][1]));
            *(float4*)&crow[4] = make_float4(lo2(acc2[i][2]), hi2(acc2[i][2]),
                                             lo2(acc2[i][3]), hi2(acc2[i][3]));
        }
    }
}

// ---------------- CSR build ----------------
__global__ void k_hist() {
    int e = blockIdx.x * blockDim.x + threadIdx.x;
    if (e >= EMAX) return;
    if (g_emask[e]) atomicAdd(&g_deg[g_dst[e]], 1);
}

__global__ void k_scan(int N) {
    __shared__ int sm[1024];
    int t = threadIdx.x;
    int chunk = (N + 1023) >> 10;
    int beg = t * chunk;
    int s = 0;
    for (int i = 0; i < chunk; i++) {
        int idx = beg + i;
        if (idx < N) s += g_deg[idx];
    }
    sm[t] = s;
    __syncthreads();
    for (int off = 1; off < 1024; off <<= 1) {
        int x = (t >= off) ? sm[t - off] : 0;
        __syncthreads();
        sm[t] += x;
        __syncthreads();
    }
    int excl = sm[t] - s;
    int run = excl;
    for (int i = 0; i < chunk; i++) {
        int idx = beg + i;
        if (idx < N) {
            g_rowptr[idx] = run;
            g_cursor[idx] = run;
            run += g_deg[idx];
        }
    }
    if (t == 1023) g_rowptr[N] = sm[1023];
}

__global__ void k_scatter() {
    int e = blockIdx.x * blockDim.x + threadIdx.x;
    if (e >= EMAX) return;
    if (g_emask[e]) {
        int p = atomicAdd(&g_cursor[g_dst[e]], 1);
        g_elist[p] = e;
    }
}

// ---------------- PNA aggregation + fused score (warp per node) ------------
__global__ void k_aggregate(const float* __restrict__ edge_attr, float avg_log,
                            const float* __restrict__ xin, int N)
{
    int warp = (blockIdx.x * blockDim.x + threadIdx.x) >> 5;
    int lane = threadIdx.x & 31;
    if (warp >= N) return;
    int n = warp;
    int c4 = lane * 4;

    float4 wc[8];
#pragma unroll
    for (int j = 0; j < 8; j++) wc[j] = *(const float4*)&g_Wc[j * FD + c4];
    float4 cv = *(const float4*)&g_cvec[c4];
    float4 xd4 = *(const float4*)&g_nds[(size_t)n * 384 + c4];
    float4 xdv = make_float4(xd4.x + cv.x, xd4.y + cv.y, xd4.z + cv.z, xd4.w + cv.w);

    int beg = g_rowptr[n], end = g_rowptr[n + 1];
    float4 sum = make_float4(0.f, 0.f, 0.f, 0.f);
    float4 sq  = make_float4(0.f, 0.f, 0.f, 0.f);
    float4 mx  = make_float4(-INFINITY, -INFINITY, -INFINITY, -INFINITY);
    float4 mn  = make_float4( INFINITY,  INFINITY,  INFINITY,  INFINITY);

    int e_nxt = 0, s_nxt = 0;
    if (beg < end) { e_nxt = g_elist[beg]; s_nxt = g_src[e_nxt]; }
    for (int i = beg; i < end; i++) {
        int e = e_nxt, s = s_nxt;
        if (i + 1 < end) { e_nxt = g_elist[i + 1]; s_nxt = g_src[e_nxt]; }
        float4 ea0 = *(const float4*)&edge_attr[(size_t)e * 8];
        float4 ea1 = *(const float4*)&edge_attr[(size_t)e * 8 + 4];
        float4 xs  = *(const float4*)&g_nds[(size_t)s * 384 + 128 + c4];
        float4 h = make_float4(xdv.x + xs.x, xdv.y + xs.y, xdv.z + xs.z, xdv.w + xs.w);
#define EAFMA(sc, jj) \
        h.x += (sc) * wc[jj].x; h.y += (sc) * wc[jj].y; \
        h.z += (sc) * wc[jj].z; h.w += (sc) * wc[jj].w;
        EAFMA(ea0.x, 0) EAFMA(ea0.y, 1) EAFMA(ea0.z, 2) EAFMA(ea0.w, 3)
        EAFMA(ea1.x, 4) EAFMA(ea1.y, 5) EAFMA(ea1.z, 6) EAFMA(ea1.w, 7)
#undef EAFMA
        sum.x += h.x; sum.y += h.y; sum.z += h.z; sum.w += h.w;
        sq.x += h.x * h.x; sq.y += h.y * h.y; sq.z += h.z * h.z; sq.w += h.w * h.w;
        mx.x = fmaxf(mx.x, h.x); mx.y = fmaxf(mx.y, h.y);
        mx.z = fmaxf(mx.z, h.z); mx.w = fmaxf(mx.w, h.w);
        mn.x = fminf(mn.x, h.x); mn.y = fminf(mn.y, h.y);
        mn.z = fminf(mn.z, h.z); mn.w = fminf(mn.w, h.w);
    }
    int cnt = end - beg;
    float denom = (cnt > 0) ? (float)cnt : 1.f;
    float inv = 1.f / denom;
    float4 mean = make_float4(sum.x * inv, sum.y * inv, sum.z * inv, sum.w * inv);
    float4 stdv;
#define STDV(cmp) { float v_ = sq.cmp * inv - mean.cmp * mean.cmp; \
                    if (v_ < 0.f) v_ = 0.f; stdv.cmp = sqrtf(v_ + 1e-5f); }
    STDV(x) STDV(y) STDV(z) STDV(w)
#undef STDV
    if (cnt == 0) {
        mx = make_float4(0.f, 0.f, 0.f, 0.f);
        mn = make_float4(0.f, 0.f, 0.f, 0.f);
    }
    float* row = g_Amat + (size_t)n * 640;
    *(float4*)&row[c4]       = mean;
    *(float4*)&row[128 + c4] = mn;
    *(float4*)&row[256 + c4] = mx;
    *(float4*)&row[384 + c4] = stdv;
    *(float4*)&row[512 + c4] = sum;

    float ld = logf(denom + 1.f);
    float a = ld / avg_log;
    float b = avg_log / ld;
    if (lane == 0) { g_sa[n] = a; g_sb[n] = b; }

    // ---- fused score: s = sigmoid((x.u0 + aggr.u1 + a*aggr.u2 + b*aggr.u3 + pbw)*winv)
    float4 xv = *(const float4*)&xin[(size_t)n * FD + c4];
    float4 u0 = *(const float4*)&g_u[c4];
    float accx = xv.x * u0.x + xv.y * u0.y + xv.z * u0.z + xv.w * u0.w;
    float acc1 = 0.f, acc2 = 0.f, acc3 = 0.f;
    float4 stats[5] = {mean, mn, mx, stdv, sum};
#pragma unroll
    for (int bb = 0; bb < 5; bb++) {
        float4 av = stats[bb];
        float4 u1 = *(const float4*)&g_u[128  + bb * 128 + c4];
        float4 u2 = *(const float4*)&g_u[768  + bb * 128 + c4];
        float4 u3 = *(const float4*)&g_u[1408 + bb * 128 + c4];
        acc1 += av.x * u1.x + av.y * u1.y + av.z * u1.z + av.w * u1.w;
        acc2 += av.x * u2.x + av.y * u2.y + av.z * u2.z + av.w * u2.w;
        acc3 += av.x * u3.x + av.y * u3.y + av.z * u3.z + av.w * u3.w;
    }
    float p = accx + acc1 + a * acc2 + b * acc3;
    for (int off = 16; off > 0; off >>= 1) p += __shfl_down_sync(0xffffffffu, p, off);
    if (lane == 0) {
        float s = (p + g_pbw) * g_winv;
        g_score[n] = 1.f / (1.f + expf(-s));
    }
}

// ---------------- per-graph top-k (bitonic, lax.top_k tie-break) ----------
__global__ void k_topk(int n_per, int k) {
    __shared__ float sv[512];
    __shared__ int   si[512];
    int g = blockIdx.x, t = threadIdx.x;
    float v = (t < n_per) ? g_score[g * n_per + t] : -INFINITY;
    sv[t] = v;
    si[t] = t;
    __syncthreads();
    for (int ks = 2; ks <= 512; ks <<= 1) {
        for (int j = ks >> 1; j > 0; j >>= 1) {
            int p = t ^ j;
            if (p > t) {
                float va = sv[t], vb = sv[p];
                int ia = si[t], ib = si[p];
                bool aFirst = (va > vb) || (va == vb && ia < ib);
                bool desc = ((t & ks) == 0);
                if (desc != aFirst) {
                    sv[t] = vb; si[t] = ib;
                    sv[p] = va; si[p] = ia;
                }
            }
            __syncthreads();
        }
    }
    if (t < k) {
        g_newidx[g * n_per + si[t]] = g * k + t;
        g_selidx[g * k + t] = g * n_per + si[t];
        g_vals[g * k + t] = sv[t];
    }
}

// ---------------- combine epilogue for selected rows (warp per new node) ---
__global__ void k_combine_sel(int Nout) {
    int warp = (blockIdx.x * blockDim.x + threadIdx.x) >> 5;
    int lane = threadIdx.x & 31;
    if (warp >= Nout) return;
    int n2 = warp, c4 = lane * 4;
    int orig = g_selidx[n2];
    float val = g_vals[n2];
    const float* y = g_Y + (size_t)n2 * 384;
    float a = g_sa[orig], b = g_sb[orig];
    float4 y1 = *(const float4*)&y[c4];
    float4 y2 = *(const float4*)&y[128 + c4];
    float4 y3 = *(const float4*)&y[256 + c4];
    float4 x0 = *(const float4*)&g_xP0[(size_t)n2 * FD + c4];
    float4 pb = *(const float4*)&g_pb[c4];
    float4 v;
    v.x = (x0.x + y1.x + a * y2.x + b * y3.x + pb.x) * val;
    v.y = (x0.y + y1.y + a * y2.y + b * y3.y + pb.y) * val;
    v.z = (x0.z + y1.z + a * y2.z + b * y3.z + pb.z) * val;
    v.w = (x0.w + y1.w + a * y2.w + b * y3.w + pb.w) * val;
    *(float4*)&g_xcur[(size_t)n2 * FD + c4] = v;
}

// ---------------- edge remap after pooling ----------------
__global__ void k_remap() {
    int e = blockIdx.x * blockDim.x + threadIdx.x;
    if (e >= EMAX) return;
    if (!g_emask[e]) { g_src[e] = 0; g_dst[e] = 0; return; }
    int s2 = g_newidx[g_src[e]];
    int d2 = g_newidx[g_dst[e]];
    bool ok = (s2 >= 0) && (d2 >= 0);
    g_emask[e] = ok ? 1 : 0;
    g_src[e] = ok ? s2 : 0;
    g_dst[e] = ok ? d2 : 0;
}

// ---------------- batch norm ----------------
__global__ void k_bnstats(int Nout) {
    int f = threadIdx.x;
    float s = 0.f, q = 0.f;
    for (int r = blockIdx.x; r < Nout; r += gridDim.x) {
        float v = g_xcur[(size_t)r * FD + f];
        s += v;
        q += v * v;
    }
    atomicAdd(&g_bnsum[f], s);
    atomicAdd(&g_bnsq[f], q);
}

__global__ void k_bnapply(int k, int Nout, const float* __restrict__ bng,
                          const float* __restrict__ bnb, float* ro, int l) {
    int g = blockIdx.x, f = threadIdx.x;
    float invN = 1.f / (float)Nout;
    float mu  = g_bnsum[f] * invN;
    float var = g_bnsq[f] * invN - mu * mu;
    float inv = 1.f / sqrtf(var + 1e-5f);
    float gam = bng[f], bet = bnb[f];
    float mx = -INFINITY, sm = 0.f;
    for (int r = 0; r < k; r++) {
        size_t idx = (size_t)(g * k + r) * FD + f;
        float v = g_xcur[idx];
        v = (v - mu) * inv * gam + bet;
        v = fmaxf(v, 0.f);
        g_xcur[idx] = v;
        mx = fmaxf(mx, v);
        sm += v;
    }
    if (ro) {
        ro[g * 512 + l * 256 + f]       = mx;
        ro[g * 512 + l * 256 + 128 + f] = sm / (float)k;
    }
}

__global__ void k_copyout(float* __restrict__ out, int n) {
    int i = blockIdx.x * blockDim.x + threadIdx.x;
    if (i < n) out[i] = g_xcur[i];
}

// ---------------- launch ----------------
extern "C" void kernel_launch(void* const* d_in, const int* in_sizes, int n_in,
                              void* d_out, int out_size)
{
    const float* x      = (const float*)d_in[0];
    const int*   ei     = (const int*)  d_in[1];
    const float* eattr  = (const float*)d_in[2];
    const float* edge_w = (const float*)d_in[4];
    const float* edge_b = (const float*)d_in[5];
    const float* pre_w  = (const float*)d_in[6];
    const float* pre_b  = (const float*)d_in[7];
    const float* post_w = (const float*)d_in[8];
    const float* post_b = (const float*)d_in[9];
    const float* lin_w  = (const float*)d_in[10];
    const float* lin_b  = (const float*)d_in[11];
    const float* bn_g   = (const float*)d_in[12];
    const float* bn_b   = (const float*)d_in[13];
    const float* pool_w = (const float*)d_in[14];
    float* out = (float*)d_out;

    float *p_xcur, *p_nds, *p_xP0, *p_Y, *p_Amat, *p_PW, *p_B1, *p_B2;
    int *p_selidx;
    cudaGetSymbolAddress((void**)&p_xcur, g_xcur);
    cudaGetSymbolAddress((void**)&p_nds,  g_nds);
    cudaGetSymbolAddress((void**)&p_xP0,  g_xP0);
    cudaGetSymbolAddress((void**)&p_Y,    g_Y);
    cudaGetSymbolAddress((void**)&p_Amat, g_Amat);
    cudaGetSymbolAddress((void**)&p_PW,   g_PW);
    cudaGetSymbolAddress((void**)&p_B1,   g_B1);
    cudaGetSymbolAddress((void**)&p_B2,   g_B2);
    cudaGetSymbolAddress((void**)&p_selidx, g_selidx);

    const float AVG = (float)(lgamma(34.0) / 33.0);  // mean log-degree (uniform hist)

    k_init_edges<<<(EMAX + 255) / 256, 256>>>(ei);

    int n_per = 500, N = NMAX;
    const int XOUT = 12500 * FD;                 // 1,600,000
    const bool wr_ro = (out_size >= XOUT + BGRAPH * 512);

    for (int l = 0; l < 2; l++) {
        int k = (n_per + 1) / 2;
        int Nout = BGRAPH * k;
        const float* xin  = (l == 0) ? x : p_xcur;
        const float* pw_l = pre_w + (size_t)l * 384 * FD;
        int ntiles  = (N + 127) / 128;
        int otiles  = (Nout + 127) / 128;

        k_prep<<<1, 128>>>(edge_w + (size_t)l * 8 * FD, edge_b + (size_t)l * FD,
                           pw_l + 256 * FD, pre_b + (size_t)l * FD,
                           post_b + (size_t)l * FD, lin_w + (size_t)l * FD * FD,
                           lin_b + (size_t)l * FD, pool_w + (size_t)l * FD);

        // PW = post_w @ lin_w  (2048x128)
        {
            dim3 g(16, 1);
            k_gemm3<<<g, 256>>>(post_w + (size_t)l * 2048 * FD,
                                lin_w + (size_t)l * FD * FD, p_PW, 2048, 128, 128, nullptr);
        }
        k_prepU<<<256, 256>>>(pool_w + (size_t)l * FD);
        k_packB1<<<(128 * 384 + 255) / 256, 256>>>(pw_l);
        k_packB2<<<(640 * 384 + 255) / 256, 256>>>();

        // nds[N, 0:256] = xin @ [Wd|Ws]  (x@P0 deferred to selected rows)
        {
            dim3 g(ntiles, 2);
            k_gemm3<<<g, 256>>>(xin, p_B1, p_nds, N, 128, 384, nullptr);
        }

        // CSR + aggregation (with fused scoring)
        k_reset<<<(N + 256) / 256, 256>>>(N);
        k_hist<<<(EMAX + 255) / 256, 256>>>();
        k_scan<<<1, 1024>>>(N);
        k_scatter<<<(EMAX + 255) / 256, 256>>>();
        k_aggregate<<<(N + 7) / 8, 256>>>(eattr, AVG, xin, N);

        k_topk<<<BGRAPH, 512>>>(n_per, k);

        // xP0[Nout,128] = xin[sel] @ P0  (P0 = first 128 rows of PW)
        {
            dim3 g(otiles, 1);
            k_gemm3<<<g, 256>>>(xin, p_PW, p_xP0, Nout, 128, 128, p_selidx);
        }
        // Y[Nout,384] = Amat[sel] @ [P1|P2|P3]
        {
            dim3 g(otiles, 3);
            k_gemm3<<<g, 256>>>(p_Amat, p_B2, p_Y, Nout, 640, 384, p_selidx);
        }
        k_combine_sel<<<(Nout + 7) / 8, 256>>>(Nout);

        k_remap<<<(EMAX + 255) / 256, 256>>>();

        k_bnstats<<<128, 128>>>(Nout);
        k_bnapply<<<BGRAPH, 128>>>(k, Nout, bn_g + (size_t)l * FD, bn_b + (size_t)l * FD,
                                   wr_ro ? out + XOUT : nullptr, l);
        n_per = k;
        N = Nout;
    }

    int nfinal = XOUT;
    if (nfinal > out_size) nfinal = out_size;
    k_copyout<<<(nfinal + 255) / 256, 256>>>(out, nfinal);
}

// round 16
// speedup vs baseline: 1.0724x; 1.0724x over previous
#include <cuda_runtime.h>
#include <math.h>

// ---------------- problem constants ----------------
#define NMAX   50000
#define EMAX   800000
#define FD     128
#define BGRAPH 100

typedef unsigned long long u64;

// ---------------- scratch (device globals; no allocation) ----------------
__device__ float g_xcur[NMAX * FD];            // current node features
__device__ float g_nds [(size_t)NMAX * 384];   // [xd | xs | x@P0]
__device__ float g_Y   [(size_t)NMAX * 384];   // [Y1 | Y2 | Y3] (selected rows)
__device__ float g_Amat[(size_t)NMAX * 640];   // [mean|mn|mx|std|sum]
__device__ float g_sa[NMAX];
__device__ float g_sb[NMAX];
__device__ int   g_src[EMAX];
__device__ int   g_dst[EMAX];
__device__ unsigned char g_emask[EMAX];
__device__ int   g_deg[NMAX + 1];
__device__ int   g_rowptr[NMAX + 1];
__device__ int   g_cursor[NMAX];
__device__ int   g_elist[EMAX];
__device__ int   g_newidx[NMAX];
__device__ int   g_selidx[NMAX];               // new index -> original node
__device__ float g_vals[NMAX];                 // new index -> topk score value
__device__ float g_score[NMAX];
__device__ float g_Wc[8 * FD];                 // edge_w @ We  (8x128)
__device__ float g_cvec[FD];                   // edge_b@We + pre_b
__device__ float g_PW[2048 * FD];              // post_w @ lin_w
__device__ float g_B1[128 * 384];              // [Wd | Ws | P0]
__device__ float g_B2[640 * 384];              // [P1 | P2 | P3]
__device__ float g_u[2048];                    // PW @ pool_w
__device__ float g_pb[FD];                     // post_b@lin_w + lin_b
__device__ float g_winv;                       // 1/||pool_w||
__device__ float g_pbw;                        // pb . pool_w
__device__ float g_bnsum[FD];
__device__ float g_bnsq [FD];

// ---------------- packed f32x2 helpers ----------------
__device__ __forceinline__ u64 dup2(float v) {
    u64 r; unsigned u = __float_as_uint(v);
    asm("mov.b64 %0, {%1, %1};" : "=l"(r) : "r"(u));
    return r;
}
__device__ __forceinline__ void fma2(u64& d, u64 a, u64 b) {
    asm("fma.rn.f32x2 %0, %1, %2, %0;" : "+l"(d) : "l"(a), "l"(b));
}
__device__ __forceinline__ float lo2(u64 v) { return __uint_as_float((unsigned)v); }
__device__ __forceinline__ float hi2(u64 v) { return __uint_as_float((unsigned)(v >> 32)); }

// ---------------- small init / utility kernels ----------------
__global__ void k_init_edges(const int* __restrict__ ei) {
    int i = blockIdx.x * blockDim.x + threadIdx.x;
    if (i >= EMAX) return;
    g_src[i] = ei[i];
    g_dst[i] = ei[EMAX + i];
    g_emask[i] = 1;
}

// deg zero + newidx fill + bn zero, one kernel
__global__ void k_reset(int N) {
    int i = blockIdx.x * blockDim.x + threadIdx.x;
    if (i <= N) g_deg[i] = 0;
    if (i < N) g_newidx[i] = -1;
    if (i < FD) { g_bnsum[i] = 0.f; g_bnsq[i] = 0.f; }
}

// ---------------- per-layer weight prep ----------------
__global__ void k_prep(const float* __restrict__ ew, const float* __restrict__ eb,
                       const float* __restrict__ We, const float* __restrict__ preb,
                       const float* __restrict__ postb, const float* __restrict__ linw,
                       const float* __restrict__ linb, const float* __restrict__ poolw) {
    int f = threadIdx.x;  // 0..127
    for (int jr = 0; jr < 8; jr++) {
        float acc = 0.f;
        for (int t = 0; t < FD; t++) acc += ew[jr * FD + t] * We[t * FD + f];
        g_Wc[jr * FD + f] = acc;
    }
    float c = preb[f];
    for (int t = 0; t < FD; t++) c += eb[t] * We[t * FD + f];
    g_cvec[f] = c;
    float p = linb[f];
    for (int t = 0; t < FD; t++) p += postb[t] * linw[t * FD + f];
    g_pb[f] = p;

    __shared__ float red[FD];
    red[f] = poolw[f] * poolw[f];
    __syncthreads();
    for (int off = 64; off > 0; off >>= 1) {
        if (f < off) red[f] += red[f + off];
        __syncthreads();
    }
    if (f == 0) g_winv = 1.f / sqrtf(red[0]);
    __syncthreads();
    red[f] = p * poolw[f];
    __syncthreads();
    for (int off = 64; off > 0; off >>= 1) {
        if (f < off) red[f] += red[f + off];
        __syncthreads();
    }
    if (f == 0) g_pbw = red[0];
}

// u = PW @ pool_w  (2048-vector), warp per row
__global__ void k_prepU(const float* __restrict__ poolw) {
    int warp = (blockIdx.x * blockDim.x + threadIdx.x) >> 5;
    int lane = threadIdx.x & 31;
    if (warp >= 2048) return;
    const float4* row = (const float4*)(g_PW + (size_t)warp * FD);
    float4 r = row[lane];
    float4 w = *(const float4*)&poolw[lane * 4];
    float acc = r.x * w.x + r.y * w.y + r.z * w.z + r.w * w.w;
    for (int off = 16; off > 0; off >>= 1) acc += __shfl_down_sync(0xffffffffu, acc, off);
    if (lane == 0) g_u[warp] = acc;
}

// pack B1 = [Wd | Ws | P0]  (128 x 384)
__global__ void k_packB1(const float* __restrict__ pw_l) {
    int i = blockIdx.x * blockDim.x + threadIdx.x;
    if (i >= 128 * 384) return;
    int k = i / 384, c = i % 384;
    float v;
    if (c < 128)      v = pw_l[k * 128 + c];
    else if (c < 256) v = pw_l[(128 + k) * 128 + (c - 128)];
    else              v = g_PW[k * 128 + (c - 256)];
    g_B1[i] = v;
}

// pack B2 = [P1 | P2 | P3] (640 x 384)
__global__ void k_packB2() {
    int i = blockIdx.x * blockDim.x + threadIdx.x;
    if (i >= 640 * 384) return;
    int k = i / 384, c = i % 384;
    g_B2[i] = g_PW[(size_t)(128 + (c >> 7) * 640 + k) * 128 + (c & 127)];
}

// ---------------- fp32 GEMM, double-buffered, packed FFMA2, row-gather -----
#define TK 16
__global__ __launch_bounds__(256, 2) void k_gemm3(
    const float* __restrict__ A, const float* __restrict__ B,
    float* __restrict__ C, int M, int K, int ldb, const int* __restrict__ rmap)
{
    __shared__ float As[2][TK][132];
    __shared__ float Bs[2][TK][128];
    int t  = threadIdx.x;
    int tx = t & 15;
    int ty = t >> 4;
    int rowBase = blockIdx.x * 128;
    int colBase = blockIdx.y * 128;

    int ar  = t >> 2;
    int akc = (t & 3) * 4;
    int brow = t >> 5;
    int bcol = (t & 31) * 4;

    int row0 = rowBase + ar;
    int row1 = rowBase + ar + 64;
    bool v0 = row0 < M, v1 = row1 < M;
    int gr0 = v0 ? (rmap ? rmap[row0] : row0) : 0;
    int gr1 = v1 ? (rmap ? rmap[row1] : row1) : 0;
    const float* a0p = A + (size_t)gr0 * K + akc;
    const float* a1p = A + (size_t)gr1 * K + akc;
    const float* b0p = B + (size_t)brow * ldb + colBase + bcol;
    const float* b1p = B + (size_t)(brow + 8) * ldb + colBase + bcol;

    float4 ra0, ra1, rb0, rb1;
    const float4 z4 = make_float4(0.f, 0.f, 0.f, 0.f);

    ra0 = v0 ? *(const float4*)a0p : z4;
    ra1 = v1 ? *(const float4*)a1p : z4;
    rb0 = *(const float4*)b0p;
    rb1 = *(const float4*)b1p;

    As[0][akc + 0][ar] = ra0.x; As[0][akc + 1][ar] = ra0.y;
    As[0][akc + 2][ar] = ra0.z; As[0][akc + 3][ar] = ra0.w;
    As[0][akc + 0][ar + 64] = ra1.x; As[0][akc + 1][ar + 64] = ra1.y;
    As[0][akc + 2][ar + 64] = ra1.z; As[0][akc + 3][ar + 64] = ra1.w;
    *(float4*)&Bs[0][brow][bcol]     = rb0;
    *(float4*)&Bs[0][brow + 8][bcol] = rb1;
    __syncthreads();

    u64 acc2[8][4];
#pragma unroll
    for (int i = 0; i < 8; i++)
#pragma unroll
        for (int j = 0; j < 4; j++) acc2[i][j] = 0ull;

    union F4U2 { float4 f; u64 u[2]; };

    int nT = K / TK;
    int buf = 0;
    for (int tile = 0; tile < nT; tile++) {
        if (tile + 1 < nT) {
            int kb = (tile + 1) * TK;
            ra0 = v0 ? *(const float4*)(a0p + kb) : z4;
            ra1 = v1 ? *(const float4*)(a1p + kb) : z4;
            rb0 = *(const float4*)(b0p + (size_t)kb * ldb);
            rb1 = *(const float4*)(b1p + (size_t)kb * ldb);
        }
#pragma unroll
        for (int kk = 0; kk < TK; kk++) {
            float a[8];
            *(float4*)&a[0] = *(float4*)&As[buf][kk][ty * 8];
            *(float4*)&a[4] = *(float4*)&As[buf][kk][ty * 8 + 4];
            F4U2 bA, bB;
            bA.f = *(float4*)&Bs[buf][kk][tx * 8];
            bB.f = *(float4*)&Bs[buf][kk][tx * 8 + 4];
            u64 bp0 = bA.u[0], bp1 = bA.u[1], bp2 = bB.u[0], bp3 = bB.u[1];
#pragma unroll
            for (int i = 0; i < 8; i++) {
                u64 a2 = dup2(a[i]);
                fma2(acc2[i][0], a2, bp0);
                fma2(acc2[i][1], a2, bp1);
                fma2(acc2[i][2], a2, bp2);
                fma2(acc2[i][3], a2, bp3);
            }
        }
        if (tile + 1 < nT) {
            int nb = buf ^ 1;
            As[nb][akc + 0][ar] = ra0.x; As[nb][akc + 1][ar] = ra0.y;
            As[nb][akc + 2][ar] = ra0.z; As[nb][akc + 3][ar] = ra0.w;
            As[nb][akc + 0][ar + 64] = ra1.x; As[nb][akc + 1][ar + 64] = ra1.y;
            As[nb][akc + 2][ar + 64] = ra1.z; As[nb][akc + 3][ar + 64] = ra1.w;
            *(float4*)&Bs[nb][brow][bcol]     = rb0;
            *(float4*)&Bs[nb][brow + 8][bcol] = rb1;
            __syncthreads();
            buf = nb;
        }
    }
#pragma unroll
    for (int i = 0; i < 8; i++) {
        int row = rowBase + ty * 8 + i;
        if (row < M) {
            float* crow = C + (size_t)row * ldb + colBase + tx * 8;
            *(float4*)&crow[0] = make_float4(lo2(acc2[i][0]), hi2(acc2[i][0]),
                                             lo2(acc2[i][1]), hi2(acc2[i][1]));
            *(float4*)&crow[4] = make_float4(lo2(acc2[i][2]), hi2(acc2[i][2]),
                                             lo2(acc2[i][3]), hi2(acc2[i][3]));
        }
    }
}

// ---------------- CSR build ----------------
__global__ void k_hist() {
    int e = blockIdx.x * blockDim.x + threadIdx.x;
    if (e >= EMAX) return;
    if (g_emask[e]) atomicAdd(&g_deg[g_dst[e]], 1);
}

__global__ void k_scan(int N) {
    __shared__ int sm[1024];
    int t = threadIdx.x;
    int chunk = (N + 1023) >> 10;
    int beg = t * chunk;
    int s = 0;
    for (int i = 0; i < chunk; i++) {
        int idx = beg + i;
        if (idx < N) s += g_deg[idx];
    }
    sm[t] = s;
    __syncthreads();
    for (int off = 1; off < 1024; off <<= 1) {
        int x = (t >= off) ? sm[t - off] : 0;
        __syncthreads();
        sm[t] += x;
        __syncthreads();
    }
    int excl = sm[t] - s;
    int run = excl;
    for (int i = 0; i < chunk; i++) {
        int idx = beg + i;
        if (idx < N) {
            g_rowptr[idx] = run;
            g_cursor[idx] = run;
            run += g_deg[idx];
        }
    }
    if (t == 1023) g_rowptr[N] = sm[1023];
}

__global__ void k_scatter() {
    int e = blockIdx.x * blockDim.x + threadIdx.x;
    if (e >= EMAX) return;
    if (g_emask[e]) {
        int p = atomicAdd(&g_cursor[g_dst[e]], 1);
        g_elist[p] = e;
    }
}

// ---------------- PNA aggregation: warp per node, float4 per lane ----------
__global__ void k_aggregate(const float* __restrict__ edge_attr, float avg_log, int N)
{
    int warp = (blockIdx.x * blockDim.x + threadIdx.x) >> 5;
    int lane = threadIdx.x & 31;
    if (warp >= N) return;
    int n = warp;
    int c4 = lane * 4;

    float4 wc[8];
#pragma unroll
    for (int j = 0; j < 8; j++) wc[j] = *(const float4*)&g_Wc[j * FD + c4];
    float4 cv = *(const float4*)&g_cvec[c4];
    float4 xd4 = *(const float4*)&g_nds[(size_t)n * 384 + c4];
    float4 xdv = make_float4(xd4.x + cv.x, xd4.y + cv.y, xd4.z + cv.z, xd4.w + cv.w);

    int beg = g_rowptr[n], end = g_rowptr[n + 1];
    float4 sum = make_float4(0.f, 0.f, 0.f, 0.f);
    float4 sq  = make_float4(0.f, 0.f, 0.f, 0.f);
    float4 mx  = make_float4(-INFINITY, -INFINITY, -INFINITY, -INFINITY);
    float4 mn  = make_float4( INFINITY,  INFINITY,  INFINITY,  INFINITY);

    int e_nxt = 0, s_nxt = 0;
    if (beg < end) { e_nxt = g_elist[beg]; s_nxt = g_src[e_nxt]; }
    for (int i = beg; i < end; i++) {
        int e = e_nxt, s = s_nxt;
        if (i + 1 < end) { e_nxt = g_elist[i + 1]; s_nxt = g_src[e_nxt]; }
        float4 ea0 = *(const float4*)&edge_attr[(size_t)e * 8];
        float4 ea1 = *(const float4*)&edge_attr[(size_t)e * 8 + 4];
        float4 xs  = *(const float4*)&g_nds[(size_t)s * 384 + 128 + c4];
        float4 h = make_float4(xdv.x + xs.x, xdv.y + xs.y, xdv.z + xs.z, xdv.w + xs.w);
#define EAFMA(sc, jj) \
        h.x += (sc) * wc[jj].x; h.y += (sc) * wc[jj].y; \
        h.z += (sc) * wc[jj].z; h.w += (sc) * wc[jj].w;
        EAFMA(ea0.x, 0) EAFMA(ea0.y, 1) EAFMA(ea0.z, 2) EAFMA(ea0.w, 3)
        EAFMA(ea1.x, 4) EAFMA(ea1.y, 5) EAFMA(ea1.z, 6) EAFMA(ea1.w, 7)
#undef EAFMA
        sum.x += h.x; sum.y += h.y; sum.z += h.z; sum.w += h.w;
        sq.x += h.x * h.x; sq.y += h.y * h.y; sq.z += h.z * h.z; sq.w += h.w * h.w;
        mx.x = fmaxf(mx.x, h.x); mx.y = fmaxf(mx.y, h.y);
        mx.z = fmaxf(mx.z, h.z); mx.w = fmaxf(mx.w, h.w);
        mn.x = fminf(mn.x, h.x); mn.y = fminf(mn.y, h.y);
        mn.z = fminf(mn.z, h.z); mn.w = fminf(mn.w, h.w);
    }
    int cnt = end - beg;
    float denom = (cnt > 0) ? (float)cnt : 1.f;
    float inv = 1.f / denom;
    float4 mean = make_float4(sum.x * inv, sum.y * inv, sum.z * inv, sum.w * inv);
    float4 stdv;
#define STDV(cmp) { float v_ = sq.cmp * inv - mean.cmp * mean.cmp; \
                    if (v_ < 0.f) v_ = 0.f; stdv.cmp = sqrtf(v_ + 1e-5f); }
    STDV(x) STDV(y) STDV(z) STDV(w)
#undef STDV
    if (cnt == 0) {
        mx = make_float4(0.f, 0.f, 0.f, 0.f);
        mn = make_float4(0.f, 0.f, 0.f, 0.f);
    }
    float* row = g_Amat + (size_t)n * 640;
    *(float4*)&row[c4]       = mean;
    *(float4*)&row[128 + c4] = mn;
    *(float4*)&row[256 + c4] = mx;
    *(float4*)&row[384 + c4] = stdv;
    *(float4*)&row[512 + c4] = sum;
    if (lane == 0) {
        float ld = logf(denom + 1.f);
        g_sa[n] = ld / avg_log;
        g_sb[n] = avg_log / ld;
    }
}

// ---------------- score via u = PW@w  (fp32, warp per node) ----------------
__global__ void k_scoreu(const float* __restrict__ xin, int N) {
    int warp = (blockIdx.x * blockDim.x + threadIdx.x) >> 5;
    int lane = threadIdx.x & 31;
    if (warp >= N) return;
    int n = warp, c4 = lane * 4;
    float4 xv = *(const float4*)&xin[(size_t)n * FD + c4];
    float4 u0 = *(const float4*)&g_u[c4];
    float accx = xv.x * u0.x + xv.y * u0.y + xv.z * u0.z + xv.w * u0.w;
    float acc1 = 0.f, acc2 = 0.f, acc3 = 0.f;
    const float* arow = g_Amat + (size_t)n * 640;
#pragma unroll
    for (int b = 0; b < 5; b++) {
        float4 av = *(const float4*)&arow[b * 128 + c4];
        float4 u1 = *(const float4*)&g_u[128  + b * 128 + c4];
        float4 u2 = *(const float4*)&g_u[768  + b * 128 + c4];
        float4 u3 = *(const float4*)&g_u[1408 + b * 128 + c4];
        acc1 += av.x * u1.x + av.y * u1.y + av.z * u1.z + av.w * u1.w;
        acc2 += av.x * u2.x + av.y * u2.y + av.z * u2.z + av.w * u2.w;
        acc3 += av.x * u3.x + av.y * u3.y + av.z * u3.z + av.w * u3.w;
    }
    float p = accx + acc1 + g_sa[n] * acc2 + g_sb[n] * acc3;
    for (int off = 16; off > 0; off >>= 1) p += __shfl_down_sync(0xffffffffu, p, off);
    if (lane == 0) {
        float s = (p + g_pbw) * g_winv;
        g_score[n] = 1.f / (1.f + expf(-s));
    }
}

// ---------------- per-graph top-k (bitonic, lax.top_k tie-break) ----------
__global__ void k_topk(int n_per, int k) {
    __shared__ float sv[512];
    __shared__ int   si[512];
    int g = blockIdx.x, t = threadIdx.x;
    float v = (t < n_per) ? g_score[g * n_per + t] : -INFINITY;
    sv[t] = v;
    si[t] = t;
    __syncthreads();
    for (int ks = 2; ks <= 512; ks <<= 1) {
        for (int j = ks >> 1; j > 0; j >>= 1) {
            int p = t ^ j;
            if (p > t) {
                float va = sv[t], vb = sv[p];
                int ia = si[t], ib = si[p];
                bool aFirst = (va > vb) || (va == vb && ia < ib);
                bool desc = ((t & ks) == 0);
                if (desc != aFirst) {
                    sv[t] = vb; si[t] = ib;
                    sv[p] = va; si[p] = ia;
                }
            }
            __syncthreads();
        }
    }
    if (t < k) {
        g_newidx[g * n_per + si[t]] = g * k + t;
        g_selidx[g * k + t] = g * n_per + si[t];
        g_vals[g * k + t] = sv[t];
    }
}

// ---------------- combine epilogue for selected rows (warp per new node) ---
__global__ void k_combine_sel(int Nout) {
    int warp = (blockIdx.x * blockDim.x + threadIdx.x) >> 5;
    int lane = threadIdx.x & 31;
    if (warp >= Nout) return;
    int n2 = warp, c4 = lane * 4;
    int orig = g_selidx[n2];
    float val = g_vals[n2];
    const float* y = g_Y + (size_t)n2 * 384;
    float a = g_sa[orig], b = g_sb[orig];
    float4 y1 = *(const float4*)&y[c4];
    float4 y2 = *(const float4*)&y[128 + c4];
    float4 y3 = *(const float4*)&y[256 + c4];
    float4 x0 = *(const float4*)&g_nds[(size_t)orig * 384 + 256 + c4];
    float4 pb = *(const float4*)&g_pb[c4];
    float4 v;
    v.x = (x0.x + y1.x + a * y2.x + b * y3.x + pb.x) * val;
    v.y = (x0.y + y1.y + a * y2.y + b * y3.y + pb.y) * val;
    v.z = (x0.z + y1.z + a * y2.z + b * y3.z + pb.z) * val;
    v.w = (x0.w + y1.w + a * y2.w + b * y3.w + pb.w) * val;
    *(float4*)&g_xcur[(size_t)n2 * FD + c4] = v;
}

// ---------------- edge remap after pooling ----------------
__global__ void k_remap() {
    int e = blockIdx.x * blockDim.x + threadIdx.x;
    if (e >= EMAX) return;
    if (!g_emask[e]) { g_src[e] = 0; g_dst[e] = 0; return; }
    int s2 = g_newidx[g_src[e]];
    int d2 = g_newidx[g_dst[e]];
    bool ok = (s2 >= 0) && (d2 >= 0);
    g_emask[e] = ok ? 1 : 0;
    g_src[e] = ok ? s2 : 0;
    g_dst[e] = ok ? d2 : 0;
}

// ---------------- batch norm ----------------
__global__ void k_bnstats(int Nout) {
    int f = threadIdx.x;
    float s = 0.f, q = 0.f;
    for (int r = blockIdx.x; r < Nout; r += gridDim.x) {
        float v = g_xcur[(size_t)r * FD + f];
        s += v;
        q += v * v;
    }
    atomicAdd(&g_bnsum[f], s);
    atomicAdd(&g_bnsq[f], q);
}

// writes normalized x to xdst (g_xcur for layer 0; d_out directly for layer 1)
__global__ void k_bnapply(int k, int Nout, const float* __restrict__ bng,
                          const float* __restrict__ bnb, float* __restrict__ xdst,
                          float* ro, int l) {
    int g = blockIdx.x, f = threadIdx.x;
    float invN = 1.f / (float)Nout;
    float mu  = g_bnsum[f] * invN;
    float var = g_bnsq[f] * invN - mu * mu;
    float inv = 1.f / sqrtf(var + 1e-5f);
    float gam = bng[f], bet = bnb[f];
    float mx = -INFINITY, sm = 0.f;
    for (int r = 0; r < k; r++) {
        size_t idx = (size_t)(g * k + r) * FD + f;
        float v = g_xcur[idx];
        v = (v - mu) * inv * gam + bet;
        v = fmaxf(v, 0.f);
        xdst[idx] = v;
        mx = fmaxf(mx, v);
        sm += v;
    }
    if (ro) {
        ro[g * 512 + l * 256 + f]       = mx;
        ro[g * 512 + l * 256 + 128 + f] = sm / (float)k;
    }
}

// ---------------- launch ----------------
extern "C" void kernel_launch(void* const* d_in, const int* in_sizes, int n_in,
                              void* d_out, int out_size)
{
    const float* x      = (const float*)d_in[0];
    const int*   ei     = (const int*)  d_in[1];
    const float* eattr  = (const float*)d_in[2];
    const float* edge_w = (const float*)d_in[4];
    const float* edge_b = (const float*)d_in[5];
    const float* pre_w  = (const float*)d_in[6];
    const float* pre_b  = (const float*)d_in[7];
    const float* post_w = (const float*)d_in[8];
    const float* post_b = (const float*)d_in[9];
    const float* lin_w  = (const float*)d_in[10];
    const float* lin_b  = (const float*)d_in[11];
    const float* bn_g   = (const float*)d_in[12];
    const float* bn_b   = (const float*)d_in[13];
    const float* pool_w = (const float*)d_in[14];
    float* out = (float*)d_out;

    float *p_xcur, *p_nds, *p_Y, *p_Amat, *p_PW, *p_B1, *p_B2;
    int *p_selidx;
    cudaGetSymbolAddress((void**)&p_xcur, g_xcur);
    cudaGetSymbolAddress((void**)&p_nds,  g_nds);
    cudaGetSymbolAddress((void**)&p_Y,    g_Y);
    cudaGetSymbolAddress((void**)&p_Amat, g_Amat);
    cudaGetSymbolAddress((void**)&p_PW,   g_PW);
    cudaGetSymbolAddress((void**)&p_B1,   g_B1);
    cudaGetSymbolAddress((void**)&p_B2,   g_B2);
    cudaGetSymbolAddress((void**)&p_selidx, g_selidx);

    const float AVG = (float)(lgamma(34.0) / 33.0);  // mean log-degree (uniform hist)

    k_init_edges<<<(EMAX + 255) / 256, 256>>>(ei);

    int n_per = 500, N = NMAX;
    const int XOUT = 12500 * FD;                 // 1,600,000
    const bool wr_ro = (out_size >= XOUT + BGRAPH * 512);

    for (int l = 0; l < 2; l++) {
        int k = (n_per + 1) / 2;
        int Nout = BGRAPH * k;
        const float* xin  = (l == 0) ? x : p_xcur;
        const float* pw_l = pre_w + (size_t)l * 384 * FD;
        int ntiles  = (N + 127) / 128;
        int otiles  = (Nout + 127) / 128;

        k_prep<<<1, 128>>>(edge_w + (size_t)l * 8 * FD, edge_b + (size_t)l * FD,
                           pw_l + 256 * FD, pre_b + (size_t)l * FD,
                           post_b + (size_t)l * FD, lin_w + (size_t)l * FD * FD,
                           lin_b + (size_t)l * FD, pool_w + (size_t)l * FD);

        // PW = post_w @ lin_w  (2048x128)
        {
            dim3 g(16, 1);
            k_gemm3<<<g, 256>>>(post_w + (size_t)l * 2048 * FD,
                                lin_w + (size_t)l * FD * FD, p_PW, 2048, 128, 128, nullptr);
        }
        k_prepU<<<256, 256>>>(pool_w + (size_t)l * FD);
        k_packB1<<<(128 * 384 + 255) / 256, 256>>>(pw_l);
        k_packB2<<<(640 * 384 + 255) / 256, 256>>>();

        // nds[N,384] = xin @ [Wd|Ws|P0]  (all rows)
        {
            dim3 g(ntiles, 3);
            k_gemm3<<<g, 256>>>(xin, p_B1, p_nds, N, 128, 384, nullptr);
        }

        // CSR + aggregation
        k_reset<<<(N + 256) / 256, 256>>>(N);
        k_hist<<<(EMAX + 255) / 256, 256>>>();
        k_scan<<<1, 1024>>>(N);
        k_scatter<<<(EMAX + 255) / 256, 256>>>();
        k_aggregate<<<(N + 7) / 8, 256>>>(eattr, AVG, N);

        // scores (fp32, u-vector) for ALL nodes, then top-k selection
        k_scoreu<<<(N + 7) / 8, 256>>>(xin, N);
        k_topk<<<BGRAPH, 512>>>(n_per, k);

        // Y[Nout,384] = Amat[sel] @ [P1|P2|P3]  (selected rows only)
        {
            dim3 g(otiles, 3);
            k_gemm3<<<g, 256>>>(p_Amat, p_B2, p_Y, Nout, 640, 384, p_selidx);
        }
        k_combine_sel<<<(Nout + 7) / 8, 256>>>(Nout);

        k_remap<<<(EMAX + 255) / 256, 256>>>();

        k_bnstats<<<128, 128>>>(Nout);
        // last layer writes normalized x straight into d_out (same values copyout copied)
        k_bnapply<<<BGRAPH, 128>>>(k, Nout, bn_g + (size_t)l * FD, bn_b + (size_t)l * FD,
                                   (l == 1) ? out : p_xcur,
                                   wr_ro ? out + XOUT : nullptr, l);
        n_per = k;
        N = Nout;
    }
}